// round 1
// baseline (speedup 1.0000x reference)
#include <cuda_runtime.h>
#include <math.h>

// Problem constants
#define D_MODEL   1024
#define SEQ_LEN   32768
#define NCHUNK    256                       // l-chunks for partial sums
#define L_PER_CHUNK (SEQ_LEN / NCHUNK)      // 128
#define DBLK      256                       // d-threads per block
#define NDBLK     (D_MODEL / DBLK)          // 4

// Scratch (no allocation allowed in kernel_launch)
__device__ float g_partial[NCHUNK * D_MODEL];   // [chunk][d]
__device__ float g_partial2[8 * D_MODEL];       // second-stage partials
__device__ float g_signal[D_MODEL];

// fl32(2*pi) and its residual: 2*pi = C1 + C2 to ~1e-15
#define TWO_PI_F  6.283185307179586f            // rounds to 0x40C90FDB
#define C1        6.28318548202514648f          // exact value of fl32(2*pi)
#define C2       (-1.74845553e-7f)              // 2*pi - C1
#define INV_2PI   0.15915494309189535f

// ---------------------------------------------------------------------------
// Kernel 1: partial signal sums.
// grid = (NDBLK, NCHUNK), block = DBLK threads. Thread owns one d; block's
// chunk covers L_PER_CHUNK positions l. Phase is built with the same fp32
// rounding order as the reference: phi = fl(fl(2pi*x) * fl(t + p)).
// sin(phi) = __sinf(phi - k*2pi) after exact-ish Cody-Waite reduction.
// ---------------------------------------------------------------------------
__global__ void signal_partial_kernel(const float* __restrict__ inputs) {
    __shared__ float sa[L_PER_CHUNK];   // 2pi * x[l]
    __shared__ float sp[L_PER_CHUNK];   // log1p(l)

    const int d     = blockIdx.x * DBLK + threadIdx.x;
    const int chunk = blockIdx.y;
    const int l0    = chunk * L_PER_CHUNK;

    if (threadIdx.x < L_PER_CHUNK) {
        const int l = l0 + threadIdx.x;
        sa[threadIdx.x] = TWO_PI_F * inputs[l];
        sp[threadIdx.x] = log1pf((float)l);
    }
    __syncthreads();

    const float t = (float)d * (1.0f / 1023.0f);

    float acc = 0.0f;
#pragma unroll 8
    for (int j = 0; j < L_PER_CHUNK; ++j) {
        float s   = t + sp[j];
        float phi = sa[j] * s;
        float k   = rintf(phi * INV_2PI);
        float r   = fmaf(k, -C1, phi);
        r         = fmaf(k, -C2, r);
        acc      += __sinf(r);           // |r| <= pi: MUFU accurate here
    }
    g_partial[chunk * D_MODEL + d] = acc;
}

// ---------------------------------------------------------------------------
// Kernel 2: first-stage reduction. 8192 threads; thread (cpart, d) sums 32
// chunks in fixed order -> deterministic.
// ---------------------------------------------------------------------------
__global__ void reduce1_kernel() {
    const int gid   = blockIdx.x * blockDim.x + threadIdx.x;  // 0..8191
    const int d     = gid & (D_MODEL - 1);
    const int cpart = gid >> 10;                              // 0..7
    float s0 = 0.f, s1 = 0.f, s2 = 0.f, s3 = 0.f;
    const int cbase = cpart * 32;
#pragma unroll
    for (int i = 0; i < 32; i += 4) {
        s0 += g_partial[(cbase + i + 0) * D_MODEL + d];
        s1 += g_partial[(cbase + i + 1) * D_MODEL + d];
        s2 += g_partial[(cbase + i + 2) * D_MODEL + d];
        s3 += g_partial[(cbase + i + 3) * D_MODEL + d];
    }
    g_partial2[cpart * D_MODEL + d] = (s0 + s1) + (s2 + s3);
}

// ---------------------------------------------------------------------------
// Kernel 3: finish reduction into shared, then GEMV out = signal @ W^T + b.
// One warp per output row, float4 loads of W. grid=128 blocks x 256 threads.
// ---------------------------------------------------------------------------
__global__ void gemv_kernel(const float* __restrict__ W,
                            const float* __restrict__ b,
                            float* __restrict__ out) {
    __shared__ float ssig[D_MODEL];

    for (int i = threadIdx.x; i < D_MODEL; i += blockDim.x) {
        float s = 0.f;
#pragma unroll
        for (int cp = 0; cp < 8; ++cp) s += g_partial2[cp * D_MODEL + i];
        ssig[i] = s;
    }
    __syncthreads();

    const int warp = threadIdx.x >> 5;
    const int lane = threadIdx.x & 31;
    const int row  = blockIdx.x * (blockDim.x >> 5) + warp;

    const float4* w4 = (const float4*)(W + row * D_MODEL);
    float acc = 0.0f;
#pragma unroll
    for (int k = lane; k < D_MODEL / 4; k += 32) {
        float4 w = w4[k];
        const float* sg = &ssig[4 * k];
        acc = fmaf(w.x, sg[0], acc);
        acc = fmaf(w.y, sg[1], acc);
        acc = fmaf(w.z, sg[2], acc);
        acc = fmaf(w.w, sg[3], acc);
    }
#pragma unroll
    for (int off = 16; off > 0; off >>= 1)
        acc += __shfl_down_sync(0xffffffffu, acc, off);

    if (lane == 0) out[row] = acc + b[row];
}

// ---------------------------------------------------------------------------
extern "C" void kernel_launch(void* const* d_in, const int* in_sizes, int n_in,
                              void* d_out, int out_size) {
    const float* inputs = (const float*)d_in[0];   // [32768]
    const float* W      = (const float*)d_in[1];   // [1024,1024]
    const float* b      = (const float*)d_in[2];   // [1024]
    float*       out    = (float*)d_out;           // [1024]

    dim3 grid1(NDBLK, NCHUNK);
    signal_partial_kernel<<<grid1, DBLK>>>(inputs);
    reduce1_kernel<<<32, 256>>>();
    gemv_kernel<<<D_MODEL / 8, 256>>>(W, b, out);
    (void)in_sizes; (void)n_in; (void)out_size;
}

// round 2
// speedup vs baseline: 1.0013x; 1.0013x over previous
#include <cuda_runtime.h>
#include <math.h>

// Problem constants
#define D_MODEL   1024
#define SEQ_LEN   32768
#define NCHUNK    256                       // l-chunks for partial sums
#define L_PER_CHUNK (SEQ_LEN / NCHUNK)      // 128
#define DBLK      256                       // d-threads per block
#define NDBLK     (D_MODEL / DBLK)          // 4

// Scratch (no allocation allowed in kernel_launch)
__device__ float g_partial[NCHUNK * D_MODEL];   // [chunk][d]
__device__ float g_partial2[8 * D_MODEL];       // second-stage partials

#define TWO_PI_F  6.283185307179586f            // rounds to 0x40C90FDB
#define C1        6.28318548202514648f          // exact value of fl32(2*pi)
#define INV_2PI   0.15915494309189535f

// ---------------------------------------------------------------------------
// Kernel 1: partial signal sums — tuned to the MUFU floor.
// Per term: 1 LDS.64 (broadcast), 1 FFMA (phase), 1 FMUL (k-arg),
// 1 FRND (ALU pipe), 1 FFMA (range reduce), 1 MUFU.SIN, 1 FADD (acc).
// FMA pipe: 4 ops = 8 cyc/SMSP; MUFU: 8 cyc/SMSP -> balanced.
// ---------------------------------------------------------------------------
__global__ void signal_partial_kernel(const float* __restrict__ inputs) {
    __shared__ float2 sc[L_PER_CHUNK];   // (a = 2pi*x[l], b = a*log1p(l))

    const int d     = blockIdx.x * DBLK + threadIdx.x;
    const int chunk = blockIdx.y;

    if (threadIdx.x < L_PER_CHUNK) {
        const int l = chunk * L_PER_CHUNK + threadIdx.x;
        float a = TWO_PI_F * inputs[l];
        float p = log1pf((float)l);
        sc[threadIdx.x] = make_float2(a, a * p);
    }
    __syncthreads();

    const float t = (float)d * (1.0f / 1023.0f);

    float acc0 = 0.0f, acc1 = 0.0f;
#pragma unroll 16
    for (int j = 0; j < L_PER_CHUNK; j += 2) {
        float2 c0 = sc[j];
        float2 c1 = sc[j + 1];

        float phi0 = fmaf(c0.x, t, c0.y);
        float k0   = rintf(phi0 * INV_2PI);          // FRND -> ALU pipe
        float r0   = fmaf(k0, -C1, phi0);            // |r0| <= pi (+8.7e-6)
        acc0      += __sinf(r0);

        float phi1 = fmaf(c1.x, t, c1.y);
        float k1   = rintf(phi1 * INV_2PI);
        float r1   = fmaf(k1, -C1, phi1);
        acc1      += __sinf(r1);
    }
    g_partial[chunk * D_MODEL + d] = acc0 + acc1;
}

// ---------------------------------------------------------------------------
// Kernel 2: first-stage reduction. 8192 threads; thread (cpart, d) sums 32
// chunks in fixed order -> deterministic.
// ---------------------------------------------------------------------------
__global__ void reduce1_kernel() {
    const int gid   = blockIdx.x * blockDim.x + threadIdx.x;  // 0..8191
    const int d     = gid & (D_MODEL - 1);
    const int cpart = gid >> 10;                              // 0..7
    float s0 = 0.f, s1 = 0.f, s2 = 0.f, s3 = 0.f;
    const int cbase = cpart * 32;
#pragma unroll
    for (int i = 0; i < 32; i += 4) {
        s0 += g_partial[(cbase + i + 0) * D_MODEL + d];
        s1 += g_partial[(cbase + i + 1) * D_MODEL + d];
        s2 += g_partial[(cbase + i + 2) * D_MODEL + d];
        s3 += g_partial[(cbase + i + 3) * D_MODEL + d];
    }
    g_partial2[cpart * D_MODEL + d] = (s0 + s1) + (s2 + s3);
}

// ---------------------------------------------------------------------------
// Kernel 3: finish reduction into shared, then GEMV out = signal @ W^T + b.
// One warp per output row, float4 loads of W. grid=128 blocks x 256 threads.
// ---------------------------------------------------------------------------
__global__ void gemv_kernel(const float* __restrict__ W,
                            const float* __restrict__ b,
                            float* __restrict__ out) {
    __shared__ float ssig[D_MODEL];

    for (int i = threadIdx.x; i < D_MODEL; i += blockDim.x) {
        float s = 0.f;
#pragma unroll
        for (int cp = 0; cp < 8; ++cp) s += g_partial2[cp * D_MODEL + i];
        ssig[i] = s;
    }
    __syncthreads();

    const int warp = threadIdx.x >> 5;
    const int lane = threadIdx.x & 31;
    const int row  = blockIdx.x * (blockDim.x >> 5) + warp;

    const float4* w4 = (const float4*)(W + row * D_MODEL);
    float acc = 0.0f;
#pragma unroll
    for (int k = lane; k < D_MODEL / 4; k += 32) {
        float4 w = w4[k];
        const float* sg = &ssig[4 * k];
        acc = fmaf(w.x, sg[0], acc);
        acc = fmaf(w.y, sg[1], acc);
        acc = fmaf(w.z, sg[2], acc);
        acc = fmaf(w.w, sg[3], acc);
    }
#pragma unroll
    for (int off = 16; off > 0; off >>= 1)
        acc += __shfl_down_sync(0xffffffffu, acc, off);

    if (lane == 0) out[row] = acc + b[row];
}

// ---------------------------------------------------------------------------
extern "C" void kernel_launch(void* const* d_in, const int* in_sizes, int n_in,
                              void* d_out, int out_size) {
    const float* inputs = (const float*)d_in[0];   // [32768]
    const float* W      = (const float*)d_in[1];   // [1024,1024]
    const float* b      = (const float*)d_in[2];   // [1024]
    float*       out    = (float*)d_out;           // [1024]

    dim3 grid1(NDBLK, NCHUNK);
    signal_partial_kernel<<<grid1, DBLK>>>(inputs);
    reduce1_kernel<<<32, 256>>>();
    gemv_kernel<<<D_MODEL / 8, 256>>>(W, b, out);
    (void)in_sizes; (void)n_in; (void)out_size;
}

// round 3
// speedup vs baseline: 1.3378x; 1.3361x over previous
#include <cuda_runtime.h>
#include <math.h>

// Problem constants
#define D_MODEL   1024
#define SEQ_LEN   32768
#define NCHUNK    256                       // l-chunks for partial sums
#define L_PER_CHUNK (SEQ_LEN / NCHUNK)      // 128
#define DBLK      256                       // d-threads per block
#define NDBLK     (D_MODEL / DBLK)          // 4

// Scratch (no allocation allowed in kernel_launch)
__device__ float g_partial[NCHUNK * D_MODEL];   // [chunk][d]
__device__ float g_partial2[8 * D_MODEL];       // second-stage partials

#define TWO_PI_F  6.283185307179586f
#define INV_PI    0.3183098861837907f           // fl32 = 0x3EA2F983
#define PI_HI     3.14159274101257324f          // fl32(pi)
#define MAGIC     12582912.0f                   // 1.5 * 2^23

// Taylor sin coefficients (deg 9, |r| <= pi/2, err <= ~7e-6)
#define S3  (-1.6666667e-1f)
#define S5  ( 8.3333333e-3f)
#define S7  (-1.9841270e-4f)
#define S9  ( 2.7557319e-6f)

// FMA-pipe-only sin: reduce by pi (magic rounding, no FRND), sign from
// parity bit (ALU pipe), deg-9 odd Taylor. 10 FMA-pipe ops total.
__device__ __forceinline__ void sin_poly_acc(float phi, float& acc) {
    float y  = fmaf(phi, INV_PI, MAGIC);            // FFMA
    float k  = y - MAGIC;                           // FADD
    float r  = fmaf(k, -PI_HI, phi);                // FFMA, |r| <= pi/2
    unsigned par = (__float_as_uint(y) & 1u) << 31; // ALU
    float rs = __uint_as_float(__float_as_uint(r) ^ par); // ALU
    float s  = r * r;                               // FMUL
    float p  = fmaf(s, S9, S7);                     // 4x FFMA
    p        = fmaf(p, s, S5);
    p        = fmaf(p, s, S3);
    p        = fmaf(p, s, 1.0f);
    acc      = fmaf(rs, p, acc);                    // FFMA
}

// ---------------------------------------------------------------------------
// Kernel 1: partial signal sums — MUFU/FMA dual-pipe hybrid.
// Per 8 terms: 5 via __sinf (MUFU: 5x16=80 cyc; FMA: 5x2 ops=20 cyc),
// 3 via sin_poly_acc (FMA: 3x20=60 cyc). Both pipes ~80 cyc -> 10 cyc/term.
// ---------------------------------------------------------------------------
__global__ void signal_partial_kernel(const float* __restrict__ inputs) {
    __shared__ float4 sc[L_PER_CHUNK / 2];   // pairs of (a, b=a*log1p(l))

    const int d     = blockIdx.x * DBLK + threadIdx.x;
    const int chunk = blockIdx.y;

    if (threadIdx.x < L_PER_CHUNK) {
        const int l = chunk * L_PER_CHUNK + threadIdx.x;
        float a = TWO_PI_F * inputs[l];
        float p = log1pf((float)l);
        ((float2*)sc)[threadIdx.x] = make_float2(a, a * p);
    }
    __syncthreads();

    const float t = (float)d * (1.0f / 1023.0f);

    float accA = 0.0f, accB = 0.0f, accC = 0.0f, accD = 0.0f;
#pragma unroll 4
    for (int g = 0; g < L_PER_CHUNK / 8; ++g) {   // 16 groups of 8 terms
        float4 q0 = sc[g * 4 + 0];
        float4 q1 = sc[g * 4 + 1];
        float4 q2 = sc[g * 4 + 2];
        float4 q3 = sc[g * 4 + 3];

        float ph0 = fmaf(q0.x, t, q0.y);
        float ph1 = fmaf(q0.z, t, q0.w);
        float ph2 = fmaf(q1.x, t, q1.y);
        float ph3 = fmaf(q1.z, t, q1.w);
        float ph4 = fmaf(q2.x, t, q2.y);
        float ph5 = fmaf(q2.z, t, q2.w);
        float ph6 = fmaf(q3.x, t, q3.y);
        float ph7 = fmaf(q3.z, t, q3.w);

        // 5 MUFU-path terms (HW RRO handles range reduction)
        accA += __sinf(ph0);
        accB += __sinf(ph1);
        accC += __sinf(ph2);
        accD += __sinf(ph3);
        accA += __sinf(ph4);

        // 3 FMA-pipe polynomial terms
        sin_poly_acc(ph5, accB);
        sin_poly_acc(ph6, accC);
        sin_poly_acc(ph7, accD);
    }
    g_partial[chunk * D_MODEL + d] = (accA + accB) + (accC + accD);
}

// ---------------------------------------------------------------------------
// Kernel 2: first-stage reduction. 8192 threads; thread (cpart, d) sums 32
// chunks in fixed order -> deterministic.
// ---------------------------------------------------------------------------
__global__ void reduce1_kernel() {
    const int gid   = blockIdx.x * blockDim.x + threadIdx.x;  // 0..8191
    const int d     = gid & (D_MODEL - 1);
    const int cpart = gid >> 10;                              // 0..7
    float s0 = 0.f, s1 = 0.f, s2 = 0.f, s3 = 0.f;
    const int cbase = cpart * 32;
#pragma unroll
    for (int i = 0; i < 32; i += 4) {
        s0 += g_partial[(cbase + i + 0) * D_MODEL + d];
        s1 += g_partial[(cbase + i + 1) * D_MODEL + d];
        s2 += g_partial[(cbase + i + 2) * D_MODEL + d];
        s3 += g_partial[(cbase + i + 3) * D_MODEL + d];
    }
    g_partial2[cpart * D_MODEL + d] = (s0 + s1) + (s2 + s3);
}

// ---------------------------------------------------------------------------
// Kernel 3: finish reduction into shared, then GEMV out = signal @ W^T + b.
// One warp per output row, float4 loads of W. grid=128 blocks x 256 threads.
// ---------------------------------------------------------------------------
__global__ void gemv_kernel(const float* __restrict__ W,
                            const float* __restrict__ b,
                            float* __restrict__ out) {
    __shared__ float ssig[D_MODEL];

    for (int i = threadIdx.x; i < D_MODEL; i += blockDim.x) {
        float s = 0.f;
#pragma unroll
        for (int cp = 0; cp < 8; ++cp) s += g_partial2[cp * D_MODEL + i];
        ssig[i] = s;
    }
    __syncthreads();

    const int warp = threadIdx.x >> 5;
    const int lane = threadIdx.x & 31;
    const int row  = blockIdx.x * (blockDim.x >> 5) + warp;

    const float4* w4 = (const float4*)(W + row * D_MODEL);
    float acc = 0.0f;
#pragma unroll
    for (int k = lane; k < D_MODEL / 4; k += 32) {
        float4 w = w4[k];
        const float* sg = &ssig[4 * k];
        acc = fmaf(w.x, sg[0], acc);
        acc = fmaf(w.y, sg[1], acc);
        acc = fmaf(w.z, sg[2], acc);
        acc = fmaf(w.w, sg[3], acc);
    }
#pragma unroll
    for (int off = 16; off > 0; off >>= 1)
        acc += __shfl_down_sync(0xffffffffu, acc, off);

    if (lane == 0) out[row] = acc + b[row];
}

// ---------------------------------------------------------------------------
extern "C" void kernel_launch(void* const* d_in, const int* in_sizes, int n_in,
                              void* d_out, int out_size) {
    const float* inputs = (const float*)d_in[0];   // [32768]
    const float* W      = (const float*)d_in[1];   // [1024,1024]
    const float* b      = (const float*)d_in[2];   // [1024]
    float*       out    = (float*)d_out;           // [1024]

    dim3 grid1(NDBLK, NCHUNK);
    signal_partial_kernel<<<grid1, DBLK>>>(inputs);
    reduce1_kernel<<<32, 256>>>();
    gemv_kernel<<<D_MODEL / 8, 256>>>(W, b, out);
    (void)in_sizes; (void)n_in; (void)out_size;
}